// round 2
// baseline (speedup 1.0000x reference)
#include <cuda_runtime.h>

#define D 4096
#define E 64
#define BM 64
#define BK 32
#define NTHREADS 128
#define MAXBLK 512
#define MAXT 16384

// ---- scratch (device globals; no allocation allowed) ----
__device__ float g_Ppart[MAXBLK * E];
__device__ float g_Mpart[MAXBLK * E];
__device__ int   g_topidx[MAXT];
__device__ float g_topprob[MAXT];
__device__ float g_P[E];
__device__ float g_M[E];

__device__ __forceinline__ unsigned long long ffma2(unsigned long long a,
                                                    unsigned long long b,
                                                    unsigned long long c) {
    unsigned long long d;
    asm("fma.rn.f32x2 %0, %1, %2, %3;" : "=l"(d) : "l"(a), "l"(b), "l"(c));
    return d;
}

// Fused router: GEMM (fp32, FFMA2) + bias + softmax + top-1 + partial P/M sums.
// Block = 64 tokens x 64 experts. Thread tile = 8 tokens (4 f32x2 pairs) x 4 experts.
__global__ __launch_bounds__(NTHREADS) void router_kernel(
    const float* __restrict__ x, const float* __restrict__ W,
    const float* __restrict__ bias, float* __restrict__ out, int T)
{
    __shared__ __align__(16) float  xs[BK][BM + 2];   // [k][token], token-pair friendly
    __shared__ __align__(16) float2 wsd[BK][E];       // W duplicated {w,w} for f32x2
    __shared__ float lsm[BM][E + 1];                  // logits (padded rows)
    __shared__ float bs[E];
    __shared__ float red_m[BM], red_s[BM], red_p[BM];
    __shared__ int   red_i[BM];
    __shared__ float Pp[2][E];

    const int tid = threadIdx.x;
    const int tx  = tid & 15;        // expert group: experts tx + 16j
    const int ty  = tid >> 4;        // token group: tokens 8*ty .. 8*ty+7
    const size_t t0 = (size_t)blockIdx.x * BM;

    if (tid < E) bs[tid] = bias[tid];

    unsigned long long acc[4][4];
#pragma unroll
    for (int p = 0; p < 4; p++)
#pragma unroll
        for (int j = 0; j < 4; j++) acc[p][j] = 0ull;

    for (int k0 = 0; k0 < D; k0 += BK) {
        // load x tile: 64 tokens x 32 k  (512 float4, 4 per thread), store transposed
#pragma unroll
        for (int r = 0; r < 4; r++) {
            int idx = tid + r * NTHREADS;
            int row = idx >> 3;          // token 0..63
            int c4  = idx & 7;           // float4 within the 32-k row
            float4 v = *(const float4*)(x + (t0 + row) * D + k0 + c4 * 4);
            xs[c4 * 4 + 0][row] = v.x;
            xs[c4 * 4 + 1][row] = v.y;
            xs[c4 * 4 + 2][row] = v.z;
            xs[c4 * 4 + 3][row] = v.w;
        }
        // load W tile: 32 k x 64 experts (512 float4, 4 per thread), duplicated lanes
#pragma unroll
        for (int r = 0; r < 4; r++) {
            int idx = tid + r * NTHREADS;
            int row = idx >> 4;          // k row 0..31
            int c4  = idx & 15;
            float4 v = *(const float4*)(W + (size_t)(k0 + row) * E + c4 * 4);
            wsd[row][c4 * 4 + 0] = make_float2(v.x, v.x);
            wsd[row][c4 * 4 + 1] = make_float2(v.y, v.y);
            wsd[row][c4 * 4 + 2] = make_float2(v.z, v.z);
            wsd[row][c4 * 4 + 3] = make_float2(v.w, v.w);
        }
        __syncthreads();
#pragma unroll
        for (int kk = 0; kk < BK; kk++) {
            unsigned long long a[4], b[4];
#pragma unroll
            for (int p = 0; p < 4; p++)
                a[p] = *(const unsigned long long*)&xs[kk][8 * ty + 2 * p];
#pragma unroll
            for (int j = 0; j < 4; j++)
                b[j] = *(const unsigned long long*)&wsd[kk][tx + 16 * j];
#pragma unroll
            for (int p = 0; p < 4; p++)
#pragma unroll
                for (int j = 0; j < 4; j++)
                    acc[p][j] = ffma2(a[p], b[j], acc[p][j]);
        }
        __syncthreads();
    }

    // spill logits to smem
#pragma unroll
    for (int p = 0; p < 4; p++)
#pragma unroll
        for (int j = 0; j < 4; j++) {
            union { unsigned long long u; float2 f; } cv;
            cv.u = acc[p][j];
            int trow = 8 * ty + 2 * p;
            int e    = tx + 16 * j;
            lsm[trow][e]     = cv.f.x;
            lsm[trow + 1][e] = cv.f.y;
        }
    __syncthreads();

    // phase 1: per-token max / first-index argmax / sum of exp
    if (tid < BM) {
        int t = tid;
        float m = -1e30f; int bi = 0;
#pragma unroll 8
        for (int e = 0; e < E; e++) {
            float v = lsm[t][e] + bs[e];
            if (v > m) { m = v; bi = e; }   // strict '>' => first occurrence wins
        }
        float ssum = 0.f;
#pragma unroll 8
        for (int e = 0; e < E; e++)
            ssum += __expf(lsm[t][e] + bs[e] - m);
        float rs = 1.0f / ssum;             // = top prob (exp(0)/sum)
        red_m[t] = m; red_s[t] = rs; red_i[t] = bi; red_p[t] = rs;
        g_topidx[t0 + t]  = bi;
        g_topprob[t0 + t] = rs;
    }
    __syncthreads();

    // phase 2: write full softmax probs to out, accumulate per-expert P partials
    {
        int e  = tid & 63;
        int th = tid >> 6;
        float Psum = 0.f;
        float be = bs[e];
        for (int t = th * 32; t < th * 32 + 32; t++) {
            float pv = __expf(lsm[t][e] + be - red_m[t]) * red_s[t];
            out[(t0 + t) * E + e] = pv;
            Psum += pv;
        }
        Pp[th][e] = Psum;
    }
    __syncthreads();

    // deterministic per-block M_e (routed mass) + partial stores
    if (tid < E) {
        int e = tid;
        float Msum = 0.f;
        for (int t = 0; t < BM; t++)
            if (red_i[t] == e) Msum += red_p[t];
        g_Ppart[blockIdx.x * E + e] = Pp[0][e] + Pp[1][e];
        g_Mpart[blockIdx.x * E + e] = Msum;
    }
}

// Reduce partials -> P_e, M_e; compute aux loss; append if room in d_out.
__global__ void reduce_kernel(float* __restrict__ out, int T, int nblk, int out_size)
{
    __shared__ float s[E];
    int e = threadIdx.x;   // 64 threads
    float P = 0.f, M = 0.f;
    for (int b = 0; b < nblk; b++) {
        P += g_Ppart[b * E + e];
        M += g_Mpart[b * E + e];
    }
    g_P[e] = P; g_M[e] = M;
    float Tf = (float)T;
    s[e] = (M / Tf) * (P / Tf);
    __syncthreads();
    if (e == 0) {
        float acc = 0.f;
        for (int i = 0; i < E; i++) acc += s[i];
        float aux = 0.01f * 64.0f * acc;
        if (out_size > T * E) out[(size_t)T * E] = aux;  // aux_loss, if concatenated
    }
}

// Capacity fixup: zero rows of tokens whose exact prefix mass exceeds capacity.
// For this distribution M_e (~36) << capacity (256), so the slow path never runs;
// the fast path is one LDG per token.
__global__ void fixup_kernel(float* __restrict__ out, int T, float cap)
{
    int t = blockIdx.x * blockDim.x + threadIdx.x;
    if (t >= T) return;
    int e = g_topidx[t];
    float M = g_M[e];
    if (M <= cap) return;           // whole expert under capacity -> all assigned
    float p = g_topprob[t];
    float prefix = 0.f;
    for (int t2 = 0; t2 < T; t2++) {
        if (g_topidx[t2] == e) {
            float p2 = g_topprob[t2];
            if (p2 > p || (p2 == p && t2 <= t)) prefix += p2;
        }
    }
    if (prefix > cap) {
#pragma unroll
        for (int j = 0; j < E; j++) out[(size_t)t * E + j] = 0.f;
    }
}

extern "C" void kernel_launch(void* const* d_in, const int* in_sizes, int n_in,
                              void* d_out, int out_size)
{
    const float* x    = (const float*)d_in[0];
    const float* W    = (const float*)d_in[1];
    const float* bias = (const float*)d_in[2];
    float* out = (float*)d_out;

    int T = in_sizes[0] / D;                 // 16384
    int nblk = T / BM;                       // 256
    float cap = (float)(int)((double)T / (double)E);  // 256

    router_kernel<<<nblk, NTHREADS>>>(x, W, bias, out, T);
    reduce_kernel<<<1, E>>>(out, T, nblk, out_size);
    fixup_kernel<<<(T + 255) / 256, 256>>>(out, T, cap);
}

// round 4
// speedup vs baseline: 1.4776x; 1.4776x over previous
#include <cuda_runtime.h>

#define D 4096
#define E 64
#define BM 64
#define BK 32
#define NT 128
#define MAXBLK 512
#define MAXT 16384
#define XS_STRIDE 66

// ---- scratch (device globals; no allocation allowed) ----
__device__ float g_Ppart[MAXBLK * E];
__device__ float g_Mpart[MAXBLK * E];
__device__ int   g_topidx[MAXT];
__device__ float g_topprob[MAXT];
__device__ float g_P[E];
__device__ float g_M[E];

__device__ __forceinline__ unsigned long long ffma2(unsigned long long a,
                                                    unsigned long long b,
                                                    unsigned long long c) {
    unsigned long long d;
    asm("fma.rn.f32x2 %0, %1, %2, %3;" : "=l"(d) : "l"(a), "l"(b), "l"(c));
    return d;
}

__device__ __forceinline__ unsigned long long dup2(float w) {
    unsigned long long d;
    asm("mov.b64 %0, {%1, %1};" : "=l"(d) : "f"(w));
    return d;
}

__global__ __launch_bounds__(NT) void router_kernel(
    const float* __restrict__ x, const float* __restrict__ W,
    const float* __restrict__ bias, float* __restrict__ out, int T)
{
    // tiles and logits overlaid: tiles dead once mainloop finishes
    __shared__ union {
        struct {
            float xs[2][BK][XS_STRIDE];   // [buf][k][token]
            float ws[2][BK][E];           // [buf][k][expert], plain f32
        } t;
        float lsm[BM][E + 1];             // logits
    } smA;
    __shared__ float bs[E];
    __shared__ float red_m[BM], red_s[BM], red_p[BM];
    __shared__ int   red_i[BM];
    __shared__ float Pp[2][E];

    const int tid = threadIdx.x;
    const int tx  = tid & 15;          // expert group: experts tx + 16j
    const int ty  = tid >> 4;          // token group: tokens 8*ty .. 8*ty+7
    const size_t t0 = (size_t)blockIdx.x * BM;

    if (tid < E) bs[tid] = bias[tid];

    // gmem load geometry (4 rounds of 128 threads each)
    const int xrow0 = tid >> 3;        // token row 0..15 (+16r)
    const int xc4   = tid & 7;         // float4 within 32-k row
    const int wrow0 = tid >> 4;        // k row 0..7 (+8r)
    const int wc4   = tid & 15;
    const float* xg = x + (t0 + xrow0) * D + xc4 * 4;
    const float* wg = W + (size_t)wrow0 * E + wc4 * 4;

    float4 xv[4], wv[4];
#pragma unroll
    for (int r = 0; r < 4; r++) {
        xv[r] = *(const float4*)(xg + (size_t)(16 * r) * D);
        wv[r] = *(const float4*)(wg + (size_t)(8 * r) * E);
    }
#pragma unroll
    for (int r = 0; r < 4; r++) {
        int row  = xrow0 + 16 * r;
        smA.t.xs[0][xc4 * 4 + 0][row] = xv[r].x;
        smA.t.xs[0][xc4 * 4 + 1][row] = xv[r].y;
        smA.t.xs[0][xc4 * 4 + 2][row] = xv[r].z;
        smA.t.xs[0][xc4 * 4 + 3][row] = xv[r].w;
        int krow = wrow0 + 8 * r;
        *(float4*)&smA.t.ws[0][krow][wc4 * 4] = wv[r];
    }
    __syncthreads();

    unsigned long long acc[4][4];
#pragma unroll
    for (int p = 0; p < 4; p++)
#pragma unroll
        for (int j = 0; j < 4; j++) acc[p][j] = 0ull;

#pragma unroll 1
    for (int k0 = 0; k0 < D; k0 += BK) {
        const int  buf  = (k0 >> 5) & 1;
        const bool more = (k0 + BK) < D;
        if (more) {    // prefetch next tile into registers (overlaps compute)
#pragma unroll
            for (int r = 0; r < 4; r++) {
                xv[r] = *(const float4*)(xg + (k0 + BK) + (size_t)(16 * r) * D);
                wv[r] = *(const float4*)(wg + (size_t)(k0 + BK) * E + (size_t)(8 * r) * E);
            }
        }
        const float* xb = &smA.t.xs[buf][0][8 * ty];
        const float* wb = &smA.t.ws[buf][0][tx];
#pragma unroll
        for (int kk = 0; kk < BK; kk++) {
            unsigned long long a[4], b[4];
#pragma unroll
            for (int p = 0; p < 4; p++)
                a[p] = *(const unsigned long long*)(xb + kk * XS_STRIDE + 2 * p);
#pragma unroll
            for (int j = 0; j < 4; j++)
                b[j] = dup2(wb[kk * E + 16 * j]);
#pragma unroll
            for (int p = 0; p < 4; p++)
#pragma unroll
                for (int j = 0; j < 4; j++)
                    acc[p][j] = ffma2(a[p], b[j], acc[p][j]);
        }
        if (more) {    // store prefetched tile to alternate buffer
#pragma unroll
            for (int r = 0; r < 4; r++) {
                int row  = xrow0 + 16 * r;
                smA.t.xs[buf ^ 1][xc4 * 4 + 0][row] = xv[r].x;
                smA.t.xs[buf ^ 1][xc4 * 4 + 1][row] = xv[r].y;
                smA.t.xs[buf ^ 1][xc4 * 4 + 2][row] = xv[r].z;
                smA.t.xs[buf ^ 1][xc4 * 4 + 3][row] = xv[r].w;
                int krow = wrow0 + 8 * r;
                *(float4*)&smA.t.ws[buf ^ 1][krow][wc4 * 4] = wv[r];
            }
        }
        __syncthreads();
    }

    // spill logits (overlays the now-dead tile buffers)
#pragma unroll
    for (int p = 0; p < 4; p++)
#pragma unroll
        for (int j = 0; j < 4; j++) {
            union { unsigned long long u; float2 f; } cv;
            cv.u = acc[p][j];
            int trow = 8 * ty + 2 * p;
            int e    = tx + 16 * j;
            smA.lsm[trow][e]     = cv.f.x;
            smA.lsm[trow + 1][e] = cv.f.y;
        }
    __syncthreads();

    // phase 1: per-token max / first-index argmax / 1/sum(exp)
    if (tid < BM) {
        int t = tid;
        float m = -1e30f; int bi = 0;
#pragma unroll 8
        for (int e = 0; e < E; e++) {
            float v = smA.lsm[t][e] + bs[e];
            if (v > m) { m = v; bi = e; }     // strict '>' => first occurrence
        }
        float ssum = 0.f;
#pragma unroll 8
        for (int e = 0; e < E; e++)
            ssum += __expf(smA.lsm[t][e] + bs[e] - m);
        float rs = 1.0f / ssum;               // top prob
        red_m[t] = m; red_s[t] = rs; red_i[t] = bi; red_p[t] = rs;
        g_topidx[t0 + t]  = bi;
        g_topprob[t0 + t] = rs;
    }
    __syncthreads();

    // phase 2: write full softmax probs; accumulate per-expert P partials
    {
        int e  = tid & 63;
        int th = tid >> 6;
        float Psum = 0.f;
        float be = bs[e];
        for (int t = th * 32; t < th * 32 + 32; t++) {
            float pv = __expf(smA.lsm[t][e] + be - red_m[t]) * red_s[t];
            out[(t0 + t) * E + e] = pv;
            Psum += pv;
        }
        Pp[th][e] = Psum;
    }
    __syncthreads();

    // deterministic per-block M_e (routed mass) + partial stores
    if (tid < E) {
        int e = tid;
        float Msum = 0.f;
        for (int t = 0; t < BM; t++)
            if (red_i[t] == e) Msum += red_p[t];
        g_Ppart[blockIdx.x * E + e] = Pp[0][e] + Pp[1][e];
        g_Mpart[blockIdx.x * E + e] = Msum;
    }
}

// Reduce partials -> P_e, M_e; compute aux loss; append if room in d_out.
__global__ void reduce_kernel(float* __restrict__ out, int T, int nblk, int out_size)
{
    __shared__ float s[E];
    int e = threadIdx.x;   // 64 threads
    float P = 0.f, M = 0.f;
    for (int b = 0; b < nblk; b++) {
        P += g_Ppart[b * E + e];
        M += g_Mpart[b * E + e];
    }
    g_P[e] = P; g_M[e] = M;
    float Tf = (float)T;
    s[e] = (M / Tf) * (P / Tf);
    __syncthreads();
    if (e == 0) {
        float acc = 0.f;
        for (int i = 0; i < E; i++) acc += s[i];
        float aux = 0.01f * 64.0f * acc;
        if (out_size > T * E) out[(size_t)T * E] = aux;
    }
}

// Capacity fixup: zero rows of tokens whose exact prefix mass exceeds capacity.
// For this distribution M_e (~36) << capacity (256) -> fast path: one LDG/token.
__global__ void fixup_kernel(float* __restrict__ out, int T, float cap)
{
    int t = blockIdx.x * blockDim.x + threadIdx.x;
    if (t >= T) return;
    int e = g_topidx[t];
    float M = g_M[e];
    if (M <= cap) return;
    float p = g_topprob[t];
    float prefix = 0.f;
    for (int t2 = 0; t2 < T; t2++) {
        if (g_topidx[t2] == e) {
            float p2 = g_topprob[t2];
            if (p2 > p || (p2 == p && t2 <= t)) prefix += p2;
        }
    }
    if (prefix > cap) {
#pragma unroll
        for (int j = 0; j < E; j++) out[(size_t)t * E + j] = 0.f;
    }
}

extern "C" void kernel_launch(void* const* d_in, const int* in_sizes, int n_in,
                              void* d_out, int out_size)
{
    const float* x    = (const float*)d_in[0];
    const float* W    = (const float*)d_in[1];
    const float* bias = (const float*)d_in[2];
    float* out = (float*)d_out;

    int T = in_sizes[0] / D;                 // 16384
    int nblk = T / BM;                       // 256
    float cap = (float)(int)((double)T / (double)E);  // 256

    router_kernel<<<nblk, NT>>>(x, W, bias, out, T);
    reduce_kernel<<<1, E>>>(out, T, nblk, out_size);
    fixup_kernel<<<(T + 255) / 256, 256>>>(out, T, cap);
}

// round 7
// speedup vs baseline: 1.7896x; 1.2111x over previous
#include <cuda_runtime.h>
#include <cuda_bf16.h>
#include <cstdint>

#define D 4096
#define E 64
#define BM 64            // tokens per CTA
#define BK 32            // k per chunk
#define NT 256
#define NCHUNK (D / BK)  // 128
#define AST 40           // smem row stride in bf16 elems (80 B)
#define MAXBLK 256
#define MAXT 16384

// ---- device scratch ----
__device__ __nv_bfloat16 g_whT[E * D];   // W^T hi  [n][k]
__device__ __nv_bfloat16 g_wlT[E * D];   // W^T lo  [n][k]
__device__ float g_Ppart[MAXBLK * E];
__device__ float g_Mpart[MAXBLK * E];
__device__ int   g_topidx[MAXT];
__device__ float g_topprob[MAXT];
__device__ float g_P[E];
__device__ float g_M[E];

__device__ __forceinline__ uint32_t smem_u32(const void* p) {
    uint32_t a;
    asm("{ .reg .u64 t; cvta.to.shared.u64 t, %1; cvt.u32.u64 %0, t; }"
        : "=r"(a) : "l"(p));
    return a;
}

__device__ __forceinline__ void ldsm_x4(uint32_t& r0, uint32_t& r1,
                                        uint32_t& r2, uint32_t& r3, uint32_t addr) {
    asm volatile("ldmatrix.sync.aligned.m8n8.x4.shared.b16 {%0,%1,%2,%3}, [%4];"
                 : "=r"(r0), "=r"(r1), "=r"(r2), "=r"(r3) : "r"(addr));
}

__device__ __forceinline__ void mma_bf16(float* c, const uint32_t* a,
                                         uint32_t b0, uint32_t b1) {
    asm volatile(
        "mma.sync.aligned.m16n8k16.row.col.f32.bf16.bf16.f32 "
        "{%0,%1,%2,%3}, {%4,%5,%6,%7}, {%8,%9}, {%0,%1,%2,%3};"
        : "+f"(c[0]), "+f"(c[1]), "+f"(c[2]), "+f"(c[3])
        : "r"(a[0]), "r"(a[1]), "r"(a[2]), "r"(a[3]), "r"(b0), "r"(b1));
}

// split (a,b) fp32 -> hi bf16x2 (a in low half) + residual bf16x2
__device__ __forceinline__ void split2(float a, float b, uint32_t& hi, uint32_t& lo) {
    asm("cvt.rn.satfinite.bf16x2.f32 %0, %1, %2;" : "=r"(hi) : "f"(b), "f"(a));
    float ah = __uint_as_float(hi << 16);
    float bh = __uint_as_float(hi & 0xFFFF0000u);
    float ar = a - ah, br = b - bh;
    asm("cvt.rn.satfinite.bf16x2.f32 %0, %1, %2;" : "=r"(lo) : "f"(br), "f"(ar));
}

// ---- W transpose + split (every launch; deterministic; ~2us) ----
__global__ void wsplit_kernel(const float* __restrict__ W) {
    int n = blockIdx.x;
    for (int k = threadIdx.x; k < D; k += blockDim.x) {
        float w = W[(size_t)k * E + n];
        __nv_bfloat16 h = __float2bfloat16(w);
        g_whT[n * D + k] = h;
        g_wlT[n * D + k] = __float2bfloat16(w - __bfloat162float(h));
    }
}

// ---- fused router: HMMA GEMM + softmax + top1 + partials ----
__global__ __launch_bounds__(NT) void router_kernel(
    const float* __restrict__ x, const float* __restrict__ bias,
    float* __restrict__ out, int T)
{
    __shared__ union {
        struct {
            __align__(16) unsigned short ah[2][BM * AST];
            __align__(16) unsigned short al[2][BM * AST];
            __align__(16) unsigned short bh[2][E * AST];
            __align__(16) unsigned short bl[2][E * AST];
        } t;                                     // 40960 B
        float lsm[BM][E + 1];                    // 16640 B (overlay)
    } smA;
    __shared__ float bs[E];
    __shared__ float red_m[BM], red_s[BM], red_p[BM];
    __shared__ int   red_i[BM];
    __shared__ float Pp[4][E];

    const int tid = threadIdx.x;
    const int wid = tid >> 5;
    const int lid = tid & 31;
    const size_t t0 = (size_t)blockIdx.x * BM;

    if (tid < E) bs[tid] = bias[tid];

    // load geometry: row = tid>>2 (0..63), kq = tid&3 (8 k-values each)
    const int row = tid >> 2;
    const int kq  = tid & 3;
    const float* xg = x + (t0 + row) * D + kq * 8;
    const unsigned char* whg = (const unsigned char*)g_whT + (size_t)row * D * 2 + kq * 16;
    const unsigned char* wlg = (const unsigned char*)g_wlT + (size_t)row * D * 2 + kq * 16;

    // warp tile: m16 x n32
    const int m_base = (wid >> 1) * 16;
    const int n_base = (wid & 1) * 32;

    // smem addresses
    const uint32_t ahb[2] = { smem_u32(&smA.t.ah[0][0]), smem_u32(&smA.t.ah[1][0]) };
    const uint32_t alb[2] = { smem_u32(&smA.t.al[0][0]), smem_u32(&smA.t.al[1][0]) };
    const uint32_t bhb[2] = { smem_u32(&smA.t.bh[0][0]), smem_u32(&smA.t.bh[1][0]) };
    const uint32_t blb[2] = { smem_u32(&smA.t.bl[0][0]), smem_u32(&smA.t.bl[1][0]) };

    // per-lane ldmatrix row offsets
    const int lg  = lid >> 3;           // address group 0..3
    const int lr  = lid & 7;            // row within group
    // A: groups (m0-7,k0) (m8-15,k0) (m0-7,k8) (m8-15,k8)
    const uint32_t a_off = (uint32_t)((m_base + (lg & 1) * 8 + lr) * 80 + (lg >> 1) * 16);
    // B pair p: groups (n0-7,k0) (n0-7,k8) (n8-15,k0) (n8-15,k8); +p*16 rows
    const uint32_t b_off0 = (uint32_t)((n_base + (lg >> 1) * 8 + lr) * 80 + (lg & 1) * 16);
    const uint32_t b_off1 = b_off0 + 16 * 80;

    float acc[4][4];
#pragma unroll
    for (int f = 0; f < 4; f++)
#pragma unroll
        for (int q = 0; q < 4; q++) acc[f][q] = 0.f;

    // ---- prologue: load + store chunk 0 ----
    float4 xv0, xv1; uint4 bhv, blv;
    xv0 = *(const float4*)(xg);
    xv1 = *(const float4*)(xg + 4);
    bhv = *(const uint4*)(whg);
    blv = *(const uint4*)(wlg);
    {
        uint4 qh, ql;
        split2(xv0.x, xv0.y, qh.x, ql.x);
        split2(xv0.z, xv0.w, qh.y, ql.y);
        split2(xv1.x, xv1.y, qh.z, ql.z);
        split2(xv1.z, xv1.w, qh.w, ql.w);
        *(uint4*)((unsigned char*)&smA.t.ah[0][0] + row * 80 + kq * 16) = qh;
        *(uint4*)((unsigned char*)&smA.t.al[0][0] + row * 80 + kq * 16) = ql;
        *(uint4*)((unsigned char*)&smA.t.bh[0][0] + row * 80 + kq * 16) = bhv;
        *(uint4*)((unsigned char*)&smA.t.bl[0][0] + row * 80 + kq * 16) = blv;
    }
    __syncthreads();

#pragma unroll 1
    for (int i = 0; i < NCHUNK; i++) {
        const int  buf  = i & 1;
        const bool more = (i + 1) < NCHUNK;
        if (more) {   // prefetch chunk i+1 into registers (overlaps mma)
            const int k0 = (i + 1) * BK;
            xv0 = *(const float4*)(xg + k0);
            xv1 = *(const float4*)(xg + k0 + 4);
            bhv = *(const uint4*)(whg + k0 * 2);
            blv = *(const uint4*)(wlg + k0 * 2);
        }
        // compute: 2 k16 steps
#pragma unroll
        for (int ks = 0; ks < 2; ks++) {
            const uint32_t koff = (uint32_t)(ks * 32);
            uint32_t ah4[4], al4[4];
            uint32_t bh8[8], bl8[8];
            ldsm_x4(ah4[0], ah4[1], ah4[2], ah4[3], ahb[buf] + a_off + koff);
            ldsm_x4(al4[0], al4[1], al4[2], al4[3], alb[buf] + a_off + koff);
            ldsm_x4(bh8[0], bh8[1], bh8[2], bh8[3], bhb[buf] + b_off0 + koff);
            ldsm_x4(bh8[4], bh8[5], bh8[6], bh8[7], bhb[buf] + b_off1 + koff);
            ldsm_x4(bl8[0], bl8[1], bl8[2], bl8[3], blb[buf] + b_off0 + koff);
            ldsm_x4(bl8[4], bl8[5], bl8[6], bl8[7], blb[buf] + b_off1 + koff);
#pragma unroll
            for (int f = 0; f < 4; f++) {
                mma_bf16(acc[f], ah4, bh8[2 * f], bh8[2 * f + 1]);   // Ah*Bh
                mma_bf16(acc[f], al4, bh8[2 * f], bh8[2 * f + 1]);   // Al*Bh
                mma_bf16(acc[f], ah4, bl8[2 * f], bl8[2 * f + 1]);   // Ah*Bl
            }
        }
        if (more) {   // store prefetched chunk to alternate buffer
            const int nb = buf ^ 1;
            uint4 qh, ql;
            split2(xv0.x, xv0.y, qh.x, ql.x);
            split2(xv0.z, xv0.w, qh.y, ql.y);
            split2(xv1.x, xv1.y, qh.z, ql.z);
            split2(xv1.z, xv1.w, qh.w, ql.w);
            *(uint4*)((unsigned char*)&smA.t.ah[nb][0] + row * 80 + kq * 16) = qh;
            *(uint4*)((unsigned char*)&smA.t.al[nb][0] + row * 80 + kq * 16) = ql;
            *(uint4*)((unsigned char*)&smA.t.bh[nb][0] + row * 80 + kq * 16) = bhv;
            *(uint4*)((unsigned char*)&smA.t.bl[nb][0] + row * 80 + kq * 16) = blv;
        }
        __syncthreads();
    }

    // ---- spill logits to smem (tiles now dead) ----
    {
        const int mr = m_base + (lid >> 2);
        const int nc = n_base + (lid & 3) * 2;
#pragma unroll
        for (int f = 0; f < 4; f++) {
            smA.lsm[mr][nc + f * 8]         = acc[f][0];
            smA.lsm[mr][nc + f * 8 + 1]     = acc[f][1];
            smA.lsm[mr + 8][nc + f * 8]     = acc[f][2];
            smA.lsm[mr + 8][nc + f * 8 + 1] = acc[f][3];
        }
    }
    __syncthreads();

    // phase 1: per-token max / first-index argmax / 1/sum(exp)
    if (tid < BM) {
        int t = tid;
        float m = -1e30f; int bi = 0;
#pragma unroll 8
        for (int e = 0; e < E; e++) {
            float v = smA.lsm[t][e] + bs[e];
            if (v > m) { m = v; bi = e; }     // strict '>' => first occurrence
        }
        float ssum = 0.f;
#pragma unroll 8
        for (int e = 0; e < E; e++)
            ssum += __expf(smA.lsm[t][e] + bs[e] - m);
        float rs = 1.0f / ssum;               // top-1 prob
        red_m[t] = m; red_s[t] = rs; red_i[t] = bi; red_p[t] = rs;
        g_topidx[t0 + t]  = bi;
        g_topprob[t0 + t] = rs;
    }
    __syncthreads();

    // phase 2: write softmax probs; per-expert P partials
    {
        int e  = tid & 63;
        int th = tid >> 6;                     // 0..3, 16 tokens each
        float Psum = 0.f;
        float be = bs[e];
        for (int t = th * 16; t < th * 16 + 16; t++) {
            float pv = __expf(smA.lsm[t][e] + be - red_m[t]) * red_s[t];
            out[(t0 + t) * E + e] = pv;
            Psum += pv;
        }
        Pp[th][e] = Psum;
    }
    __syncthreads();

    if (tid < E) {
        int e = tid;
        float Msum = 0.f;
        for (int t = 0; t < BM; t++)
            if (red_i[t] == e) Msum += red_p[t];
        g_Ppart[blockIdx.x * E + e] = Pp[0][e] + Pp[1][e] + Pp[2][e] + Pp[3][e];
        g_Mpart[blockIdx.x * E + e] = Msum;
    }
}

// ---- reduce partials -> P_e, M_e, aux loss ----
__global__ void reduce_kernel(float* __restrict__ out, int T, int nblk, int out_size)
{
    __shared__ float s[E];
    int e = threadIdx.x;
    float P = 0.f, M = 0.f;
    for (int b = 0; b < nblk; b++) {
        P += g_Ppart[b * E + e];
        M += g_Mpart[b * E + e];
    }
    g_P[e] = P; g_M[e] = M;
    float Tf = (float)T;
    s[e] = (M / Tf) * (P / Tf);
    __syncthreads();
    if (e == 0) {
        float acc = 0.f;
        for (int i = 0; i < E; i++) acc += s[i];
        float aux = 0.01f * 64.0f * acc;
        if (out_size > T * E) out[(size_t)T * E] = aux;
    }
}

// ---- capacity fixup (fast path: one LDG per token) ----
__global__ void fixup_kernel(float* __restrict__ out, int T, float cap)
{
    int t = blockIdx.x * blockDim.x + threadIdx.x;
    if (t >= T) return;
    int e = g_topidx[t];
    float M = g_M[e];
    if (M <= cap) return;
    float p = g_topprob[t];
    float prefix = 0.f;
    for (int t2 = 0; t2 < T; t2++) {
        if (g_topidx[t2] == e) {
            float p2 = g_topprob[t2];
            if (p2 > p || (p2 == p && t2 <= t)) prefix += p2;
        }
    }
    if (prefix > cap) {
#pragma unroll
        for (int j = 0; j < E; j++) out[(size_t)t * E + j] = 0.f;
    }
}

extern "C" void kernel_launch(void* const* d_in, const int* in_sizes, int n_in,
                              void* d_out, int out_size)
{
    const float* x    = (const float*)d_in[0];
    const float* W    = (const float*)d_in[1];
    const float* bias = (const float*)d_in[2];
    float* out = (float*)d_out;

    int T = in_sizes[0] / D;                          // 16384
    int nblk = T / BM;                                // 256
    float cap = (float)(int)((double)T / (double)E);  // 256

    wsplit_kernel<<<E, 256>>>(W);
    router_kernel<<<nblk, NT>>>(x, bias, out, T);
    reduce_kernel<<<1, E>>>(out, T, nblk, out_size);
    fixup_kernel<<<(T + 255) / 256, 256>>>(out, T, cap);
}

// round 8
// speedup vs baseline: 2.0943x; 1.1703x over previous
#include <cuda_runtime.h>
#include <cuda_fp16.h>
#include <cstdint>

#define D 4096
#define E 64
#define BM 64            // tokens per CTA
#define BK 32            // k per chunk
#define NT 256
#define NCHUNK (D / BK)  // 128
#define AST 40           // smem row stride in fp16 elems (80 B)
#define MAXBLK 256
#define MAXT 16384

// ---- device scratch ----
__device__ __half g_whT[E * D];          // W^T fp16  [n][k]
__device__ float g_Ppart[MAXBLK * E];
__device__ float g_Mpart[MAXBLK * E];
__device__ int   g_topidx[MAXT];
__device__ float g_topprob[MAXT];
__device__ float g_P[E];
__device__ float g_M[E];

__device__ __forceinline__ uint32_t smem_u32(const void* p) {
    uint32_t a;
    asm("{ .reg .u64 t; cvta.to.shared.u64 t, %1; cvt.u32.u64 %0, t; }"
        : "=r"(a) : "l"(p));
    return a;
}

__device__ __forceinline__ void ldsm_x4(uint32_t& r0, uint32_t& r1,
                                        uint32_t& r2, uint32_t& r3, uint32_t addr) {
    asm volatile("ldmatrix.sync.aligned.m8n8.x4.shared.b16 {%0,%1,%2,%3}, [%4];"
                 : "=r"(r0), "=r"(r1), "=r"(r2), "=r"(r3) : "r"(addr));
}

__device__ __forceinline__ void mma_f16(float* c, const uint32_t* a,
                                        uint32_t b0, uint32_t b1) {
    asm volatile(
        "mma.sync.aligned.m16n8k16.row.col.f32.f16.f16.f32 "
        "{%0,%1,%2,%3}, {%4,%5,%6,%7}, {%8,%9}, {%0,%1,%2,%3};"
        : "+f"(c[0]), "+f"(c[1]), "+f"(c[2]), "+f"(c[3])
        : "r"(a[0]), "r"(a[1]), "r"(a[2]), "r"(a[3]), "r"(b0), "r"(b1));
}

// split (a,b) fp32 -> fp16x2 hi (a in low half) + fp16x2 residual
__device__ __forceinline__ void split2h(float a, float b, uint32_t& hi, uint32_t& lo) {
    __half2 h = __floats2half2_rn(a, b);
    hi = *(uint32_t*)&h;
    float2 hf = __half22float2(h);
    __half2 l = __floats2half2_rn(a - hf.x, b - hf.y);
    lo = *(uint32_t*)&l;
}

// ---- W transpose to fp16 (every launch; deterministic; ~2us) ----
__global__ void wsplit_kernel(const float* __restrict__ W) {
    int n = blockIdx.x;
    for (int k = threadIdx.x; k < D; k += blockDim.x)
        g_whT[n * D + k] = __float2half_rn(W[(size_t)k * E + n]);
}

// ---- fused router: HMMA GEMM (2-term fp16) + softmax + top1 + partials ----
__global__ __launch_bounds__(NT) void router_kernel(
    const float* __restrict__ x, const float* __restrict__ bias,
    float* __restrict__ out, int T)
{
    __shared__ union {
        struct {
            __align__(16) unsigned short ah[2][BM * AST];
            __align__(16) unsigned short al[2][BM * AST];
            __align__(16) unsigned short bh[2][E * AST];
        } t;                                     // 30720 B
        float lsm[BM][E + 1];                    // 16640 B (overlay)
    } smA;
    __shared__ float bs[E];
    __shared__ float red_m[BM], red_s[BM], red_p[BM];
    __shared__ int   red_i[BM];
    __shared__ float Pp[4][E];

    const int tid = threadIdx.x;
    const int wid = tid >> 5;
    const int lid = tid & 31;
    const size_t t0 = (size_t)blockIdx.x * BM;

    if (tid < E) bs[tid] = bias[tid];

    // load geometry: row = tid>>2 (0..63), kq = tid&3 (8 k-values each)
    const int row = tid >> 2;
    const int kq  = tid & 3;
    const float* xg = x + (t0 + row) * D + kq * 8;
    const unsigned char* whg = (const unsigned char*)g_whT + (size_t)row * D * 2 + kq * 16;

    // warp tile: m16 x n32
    const int m_base = (wid >> 1) * 16;
    const int n_base = (wid & 1) * 32;

    const uint32_t ahb[2] = { smem_u32(&smA.t.ah[0][0]), smem_u32(&smA.t.ah[1][0]) };
    const uint32_t alb[2] = { smem_u32(&smA.t.al[0][0]), smem_u32(&smA.t.al[1][0]) };
    const uint32_t bhb[2] = { smem_u32(&smA.t.bh[0][0]), smem_u32(&smA.t.bh[1][0]) };

    // per-lane ldmatrix row offsets
    const int lg  = lid >> 3;           // address group 0..3
    const int lr  = lid & 7;            // row within group
    // A: groups (m0-7,k0) (m8-15,k0) (m0-7,k8) (m8-15,k8)
    const uint32_t a_off = (uint32_t)((m_base + (lg & 1) * 8 + lr) * 80 + (lg >> 1) * 16);
    // B pair p: groups (n0-7,k0) (n0-7,k8) (n8-15,k0) (n8-15,k8); +p*16 rows
    const uint32_t b_off0 = (uint32_t)((n_base + (lg >> 1) * 8 + lr) * 80 + (lg & 1) * 16);
    const uint32_t b_off1 = b_off0 + 16 * 80;

    float acc[4][4];
#pragma unroll
    for (int f = 0; f < 4; f++)
#pragma unroll
        for (int q = 0; q < 4; q++) acc[f][q] = 0.f;

    // ---- prologue: load + store chunk 0 ----
    float4 xv0, xv1; uint4 bhv;
    xv0 = *(const float4*)(xg);
    xv1 = *(const float4*)(xg + 4);
    bhv = *(const uint4*)(whg);
    {
        uint4 qh, ql;
        split2h(xv0.x, xv0.y, qh.x, ql.x);
        split2h(xv0.z, xv0.w, qh.y, ql.y);
        split2h(xv1.x, xv1.y, qh.z, ql.z);
        split2h(xv1.z, xv1.w, qh.w, ql.w);
        *(uint4*)((unsigned char*)&smA.t.ah[0][0] + row * 80 + kq * 16) = qh;
        *(uint4*)((unsigned char*)&smA.t.al[0][0] + row * 80 + kq * 16) = ql;
        *(uint4*)((unsigned char*)&smA.t.bh[0][0] + row * 80 + kq * 16) = bhv;
    }
    __syncthreads();

#pragma unroll 1
    for (int i = 0; i < NCHUNK; i++) {
        const int  buf  = i & 1;
        const bool more = (i + 1) < NCHUNK;
        if (more) {   // prefetch chunk i+1 into registers (overlaps mma)
            const int k0 = (i + 1) * BK;
            xv0 = *(const float4*)(xg + k0);
            xv1 = *(const float4*)(xg + k0 + 4);
            bhv = *(const uint4*)(whg + k0 * 2);
        }
        // compute: 2 k16 steps, 2 split terms
#pragma unroll
        for (int ks = 0; ks < 2; ks++) {
            const uint32_t koff = (uint32_t)(ks * 32);
            uint32_t ah4[4], al4[4], bh8[8];
            ldsm_x4(ah4[0], ah4[1], ah4[2], ah4[3], ahb[buf] + a_off + koff);
            ldsm_x4(al4[0], al4[1], al4[2], al4[3], alb[buf] + a_off + koff);
            ldsm_x4(bh8[0], bh8[1], bh8[2], bh8[3], bhb[buf] + b_off0 + koff);
            ldsm_x4(bh8[4], bh8[5], bh8[6], bh8[7], bhb[buf] + b_off1 + koff);
#pragma unroll
            for (int f = 0; f < 4; f++) {
                mma_f16(acc[f], ah4, bh8[2 * f], bh8[2 * f + 1]);   // Ah*B
                mma_f16(acc[f], al4, bh8[2 * f], bh8[2 * f + 1]);   // Al*B
            }
        }
        if (more) {   // store prefetched chunk to alternate buffer
            const int nb = buf ^ 1;
            uint4 qh, ql;
            split2h(xv0.x, xv0.y, qh.x, ql.x);
            split2h(xv0.z, xv0.w, qh.y, ql.y);
            split2h(xv1.x, xv1.y, qh.z, ql.z);
            split2h(xv1.z, xv1.w, qh.w, ql.w);
            *(uint4*)((unsigned char*)&smA.t.ah[nb][0] + row * 80 + kq * 16) = qh;
            *(uint4*)((unsigned char*)&smA.t.al[nb][0] + row * 80 + kq * 16) = ql;
            *(uint4*)((unsigned char*)&smA.t.bh[nb][0] + row * 80 + kq * 16) = bhv;
        }
        __syncthreads();
    }

    // ---- spill logits to smem (tiles now dead) ----
    {
        const int mr = m_base + (lid >> 2);
        const int nc = n_base + (lid & 3) * 2;
#pragma unroll
        for (int f = 0; f < 4; f++) {
            smA.lsm[mr][nc + f * 8]         = acc[f][0];
            smA.lsm[mr][nc + f * 8 + 1]     = acc[f][1];
            smA.lsm[mr + 8][nc + f * 8]     = acc[f][2];
            smA.lsm[mr + 8][nc + f * 8 + 1] = acc[f][3];
        }
    }
    __syncthreads();

    // phase 1: per-token max / first-index argmax / 1/sum(exp)
    if (tid < BM) {
        int t = tid;
        float m = -1e30f; int bi = 0;
#pragma unroll 8
        for (int e = 0; e < E; e++) {
            float v = smA.lsm[t][e] + bs[e];
            if (v > m) { m = v; bi = e; }     // strict '>' => first occurrence
        }
        float ssum = 0.f;
#pragma unroll 8
        for (int e = 0; e < E; e++)
            ssum += __expf(smA.lsm[t][e] + bs[e] - m);
        float rs = 1.0f / ssum;               // top-1 prob
        red_m[t] = m; red_s[t] = rs; red_i[t] = bi; red_p[t] = rs;
        g_topidx[t0 + t]  = bi;
        g_topprob[t0 + t] = rs;
    }
    __syncthreads();

    // phase 2: write softmax probs; per-expert P partials
    {
        int e  = tid & 63;
        int th = tid >> 6;                     // 0..3, 16 tokens each
        float Psum = 0.f;
        float be = bs[e];
        for (int t = th * 16; t < th * 16 + 16; t++) {
            float pv = __expf(smA.lsm[t][e] + be - red_m[t]) * red_s[t];
            out[(t0 + t) * E + e] = pv;
            Psum += pv;
        }
        Pp[th][e] = Psum;
    }
    __syncthreads();

    if (tid < E) {
        int e = tid;
        float Msum = 0.f;
        for (int t = 0; t < BM; t++)
            if (red_i[t] == e) Msum += red_p[t];
        g_Ppart[blockIdx.x * E + e] = Pp[0][e] + Pp[1][e] + Pp[2][e] + Pp[3][e];
        g_Mpart[blockIdx.x * E + e] = Msum;
    }
}

// ---- reduce partials -> P_e, M_e, aux loss ----
__global__ void reduce_kernel(float* __restrict__ out, int T, int nblk, int out_size)
{
    __shared__ float s[E];
    int e = threadIdx.x;
    float P = 0.f, M = 0.f;
    for (int b = 0; b < nblk; b++) {
        P += g_Ppart[b * E + e];
        M += g_Mpart[b * E + e];
    }
    g_P[e] = P; g_M[e] = M;
    float Tf = (float)T;
    s[e] = (M / Tf) * (P / Tf);
    __syncthreads();
    if (e == 0) {
        float acc = 0.f;
        for (int i = 0; i < E; i++) acc += s[i];
        float aux = 0.01f * 64.0f * acc;
        if (out_size > T * E) out[(size_t)T * E] = aux;
    }
}

// ---- capacity fixup (fast path: one LDG per token) ----
__global__ void fixup_kernel(float* __restrict__ out, int T, float cap)
{
    int t = blockIdx.x * blockDim.x + threadIdx.x;
    if (t >= T) return;
    int e = g_topidx[t];
    float M = g_M[e];
    if (M <= cap) return;
    float p = g_topprob[t];
    float prefix = 0.f;
    for (int t2 = 0; t2 < T; t2++) {
        if (g_topidx[t2] == e) {
            float p2 = g_topprob[t2];
            if (p2 > p || (p2 == p && t2 <= t)) prefix += p2;
        }
    }
    if (prefix > cap) {
#pragma unroll
        for (int j = 0; j < E; j++) out[(size_t)t * E + j] = 0.f;
    }
}

extern "C" void kernel_launch(void* const* d_in, const int* in_sizes, int n_in,
                              void* d_out, int out_size)
{
    const float* x    = (const float*)d_in[0];
    const float* W    = (const float*)d_in[1];
    const float* bias = (const float*)d_in[2];
    float* out = (float*)d_out;

    int T = in_sizes[0] / D;                          // 16384
    int nblk = T / BM;                                // 256
    float cap = (float)(int)((double)T / (double)E);  // 256

    wsplit_kernel<<<E, 256>>>(W);
    router_kernel<<<nblk, NT>>>(x, bias, out, T);
    reduce_kernel<<<1, E>>>(out, T, nblk, out_size);
    fixup_kernel<<<(T + 255) / 256, 256>>>(out, T, cap);
}

// round 9
// speedup vs baseline: 3.2045x; 1.5301x over previous
#include <cuda_runtime.h>
#include <cuda_fp16.h>
#include <cstdint>

#define D 4096
#define E 64
#define BM 64            // tokens per CTA
#define BK 64            // k per chunk
#define NT 256
#define NCHUNK (D / BK)  // 64
#define AST 72           // smem row stride in fp16 elems (144 B)
#define MAXBLK 256
#define MAXT 16384

// ---- device scratch ----
__device__ __half g_whT[E * D];          // W^T fp16  [n][k]
__device__ float g_Ppart[MAXBLK * E];
__device__ float g_Mpart[MAXBLK * E];
__device__ int   g_topidx[MAXT];
__device__ float g_topprob[MAXT];
__device__ float g_P[E];
__device__ float g_M[E];

__device__ __forceinline__ uint32_t smem_u32(const void* p) {
    uint32_t a;
    asm("{ .reg .u64 t; cvta.to.shared.u64 t, %1; cvt.u32.u64 %0, t; }"
        : "=r"(a) : "l"(p));
    return a;
}

__device__ __forceinline__ void ldsm_x4(uint32_t& r0, uint32_t& r1,
                                        uint32_t& r2, uint32_t& r3, uint32_t addr) {
    asm volatile("ldmatrix.sync.aligned.m8n8.x4.shared.b16 {%0,%1,%2,%3}, [%4];"
                 : "=r"(r0), "=r"(r1), "=r"(r2), "=r"(r3) : "r"(addr));
}

__device__ __forceinline__ void mma_f16(float* c, const uint32_t* a,
                                        uint32_t b0, uint32_t b1) {
    asm volatile(
        "mma.sync.aligned.m16n8k16.row.col.f32.f16.f16.f32 "
        "{%0,%1,%2,%3}, {%4,%5,%6,%7}, {%8,%9}, {%0,%1,%2,%3};"
        : "+f"(c[0]), "+f"(c[1]), "+f"(c[2]), "+f"(c[3])
        : "r"(a[0]), "r"(a[1]), "r"(a[2]), "r"(a[3]), "r"(b0), "r"(b1));
}

__device__ __forceinline__ uint32_t cvt2h(float a, float b) {
    __half2 h = __floats2half2_rn(a, b);
    return *(uint32_t*)&h;
}

// ---- W transpose to fp16 (every launch; deterministic) ----
__global__ void wsplit_kernel(const float* __restrict__ W) {
    int n = blockIdx.x;
    for (int k = threadIdx.x; k < D; k += blockDim.x)
        g_whT[n * D + k] = __float2half_rn(W[(size_t)k * E + n]);
}

// ---- fused router: HMMA GEMM (1-term fp16) + softmax + top1 + partials ----
__global__ __launch_bounds__(NT) void router_kernel(
    const float* __restrict__ x, const float* __restrict__ bias,
    float* __restrict__ out, int T)
{
    __shared__ union {
        struct {
            __align__(16) unsigned short ah[2][BM * AST];   // 2 x 9216 B
            __align__(16) unsigned short bh[2][E * AST];    // 2 x 9216 B
        } t;                                     // 36864 B
        float lsm[BM][E + 1];                    // 16640 B (overlay)
    } smA;
    __shared__ float bs[E];
    __shared__ float red_m[BM], red_s[BM], red_p[BM];
    __shared__ int   red_i[BM];
    __shared__ float Pp[4][E];

    const int tid = threadIdx.x;
    const int wid = tid >> 5;
    const int lid = tid & 31;
    const size_t t0 = (size_t)blockIdx.x * BM;

    if (tid < E) bs[tid] = bias[tid];

    // load geometry: row = tid>>2 (0..63), kq = tid&3 (16 k-values each)
    const int row = tid >> 2;
    const int kq  = tid & 3;
    const float* xg = x + (t0 + row) * D + kq * 16;
    const unsigned char* whg = (const unsigned char*)g_whT + (size_t)row * D * 2 + kq * 32;

    // warp tile: m16 x n32
    const int m_base = (wid >> 1) * 16;
    const int n_base = (wid & 1) * 32;

    const uint32_t ahb[2] = { smem_u32(&smA.t.ah[0][0]), smem_u32(&smA.t.ah[1][0]) };
    const uint32_t bhb[2] = { smem_u32(&smA.t.bh[0][0]), smem_u32(&smA.t.bh[1][0]) };

    // per-lane ldmatrix row offsets (row stride 144 B)
    const int lg  = lid >> 3;           // address group 0..3
    const int lr  = lid & 7;            // row within group
    // A: groups (m0-7,k0) (m8-15,k0) (m0-7,k8) (m8-15,k8)
    const uint32_t a_off = (uint32_t)((m_base + (lg & 1) * 8 + lr) * 144 + (lg >> 1) * 16);
    // B pair p: groups (n0-7,k0) (n0-7,k8) (n8-15,k0) (n8-15,k8); +p*16 rows
    const uint32_t b_off0 = (uint32_t)((n_base + (lg >> 1) * 8 + lr) * 144 + (lg & 1) * 16);
    const uint32_t b_off1 = b_off0 + 16 * 144;

    float acc[4][4];
#pragma unroll
    for (int f = 0; f < 4; f++)
#pragma unroll
        for (int q = 0; q < 4; q++) acc[f][q] = 0.f;

    // per-thread smem store bases (32 B per tile row segment)
    const uint32_t a_st = (uint32_t)(row * 144 + kq * 32);
    const uint32_t b_st = a_st;

    // ---- prologue: load + store chunk 0 ----
    float4 xv[4]; uint4 bv[2];
#pragma unroll
    for (int j = 0; j < 4; j++) xv[j] = *(const float4*)(xg + j * 4);
#pragma unroll
    for (int j = 0; j < 2; j++) bv[j] = *(const uint4*)(whg + j * 16);
    {
        uint4 q0 = make_uint4(cvt2h(xv[0].x, xv[0].y), cvt2h(xv[0].z, xv[0].w),
                              cvt2h(xv[1].x, xv[1].y), cvt2h(xv[1].z, xv[1].w));
        uint4 q1 = make_uint4(cvt2h(xv[2].x, xv[2].y), cvt2h(xv[2].z, xv[2].w),
                              cvt2h(xv[3].x, xv[3].y), cvt2h(xv[3].z, xv[3].w));
        *(uint4*)((unsigned char*)&smA.t.ah[0][0] + a_st)      = q0;
        *(uint4*)((unsigned char*)&smA.t.ah[0][0] + a_st + 16) = q1;
        *(uint4*)((unsigned char*)&smA.t.bh[0][0] + b_st)      = bv[0];
        *(uint4*)((unsigned char*)&smA.t.bh[0][0] + b_st + 16) = bv[1];
    }
    __syncthreads();

#pragma unroll 1
    for (int i = 0; i < NCHUNK; i++) {
        const int  buf  = i & 1;
        const bool more = (i + 1) < NCHUNK;
        if (more) {   // prefetch chunk i+1 into registers (overlaps mma)
            const int k0 = (i + 1) * BK;
#pragma unroll
            for (int j = 0; j < 4; j++) xv[j] = *(const float4*)(xg + k0 + j * 4);
#pragma unroll
            for (int j = 0; j < 2; j++) bv[j] = *(const uint4*)(whg + k0 * 2 + j * 16);
        }
        // compute: 4 k16 steps, 1 term
#pragma unroll
        for (int ks = 0; ks < 4; ks++) {
            const uint32_t koff = (uint32_t)(ks * 32);
            uint32_t a4[4], b8[8];
            ldsm_x4(a4[0], a4[1], a4[2], a4[3], ahb[buf] + a_off + koff);
            ldsm_x4(b8[0], b8[1], b8[2], b8[3], bhb[buf] + b_off0 + koff);
            ldsm_x4(b8[4], b8[5], b8[6], b8[7], bhb[buf] + b_off1 + koff);
#pragma unroll
            for (int f = 0; f < 4; f++)
                mma_f16(acc[f], a4, b8[2 * f], b8[2 * f + 1]);
        }
        if (more) {   // store prefetched chunk to alternate buffer
            const int nb = buf ^ 1;
            uint4 q0 = make_uint4(cvt2h(xv[0].x, xv[0].y), cvt2h(xv[0].z, xv[0].w),
                                  cvt2h(xv[1].x, xv[1].y), cvt2h(xv[1].z, xv[1].w));
            uint4 q1 = make_uint4(cvt2h(xv[2].x, xv[2].y), cvt2h(xv[2].z, xv[2].w),
                                  cvt2h(xv[3].x, xv[3].y), cvt2h(xv[3].z, xv[3].w));
            *(uint4*)((unsigned char*)&smA.t.ah[nb][0] + a_st)      = q0;
            *(uint4*)((unsigned char*)&smA.t.ah[nb][0] + a_st + 16) = q1;
            *(uint4*)((unsigned char*)&smA.t.bh[nb][0] + b_st)      = bv[0];
            *(uint4*)((unsigned char*)&smA.t.bh[nb][0] + b_st + 16) = bv[1];
        }
        __syncthreads();
    }

    // ---- spill logits to smem (tiles now dead) ----
    {
        const int mr = m_base + (lid >> 2);
        const int nc = n_base + (lid & 3) * 2;
#pragma unroll
        for (int f = 0; f < 4; f++) {
            smA.lsm[mr][nc + f * 8]         = acc[f][0];
            smA.lsm[mr][nc + f * 8 + 1]     = acc[f][1];
            smA.lsm[mr + 8][nc + f * 8]     = acc[f][2];
            smA.lsm[mr + 8][nc + f * 8 + 1] = acc[f][3];
        }
    }
    __syncthreads();

    // phase 1: per-token max / first-index argmax / 1/sum(exp)
    if (tid < BM) {
        int t = tid;
        float m = -1e30f; int bi = 0;
#pragma unroll 8
        for (int e = 0; e < E; e++) {
            float v = smA.lsm[t][e] + bs[e];
            if (v > m) { m = v; bi = e; }     // strict '>' => first occurrence
        }
        float ssum = 0.f;
#pragma unroll 8
        for (int e = 0; e < E; e++)
            ssum += __expf(smA.lsm[t][e] + bs[e] - m);
        float rs = 1.0f / ssum;               // top-1 prob
        red_m[t] = m; red_s[t] = rs; red_i[t] = bi; red_p[t] = rs;
        g_topidx[t0 + t]  = bi;
        g_topprob[t0 + t] = rs;
    }
    __syncthreads();

    // phase 2: write softmax probs; per-expert P partials
    {
        int e  = tid & 63;
        int th = tid >> 6;                     // 0..3, 16 tokens each
        float Psum = 0.f;
        float be = bs[e];
        for (int t = th * 16; t < th * 16 + 16; t++) {
            float pv = __expf(smA.lsm[t][e] + be - red_m[t]) * red_s[t];
            out[(t0 + t) * E + e] = pv;
            Psum += pv;
        }
        Pp[th][e] = Psum;
    }
    __syncthreads();

    if (tid < E) {
        int e = tid;
        float Msum = 0.f;
        for (int t = 0; t < BM; t++)
            if (red_i[t] == e) Msum += red_p[t];
        g_Ppart[blockIdx.x * E + e] = Pp[0][e] + Pp[1][e] + Pp[2][e] + Pp[3][e];
        g_Mpart[blockIdx.x * E + e] = Msum;
    }
}

// ---- reduce partials -> P_e, M_e, aux loss ----
__global__ void reduce_kernel(float* __restrict__ out, int T, int nblk, int out_size)
{
    __shared__ float s[E];
    int e = threadIdx.x;
    float P = 0.f, M = 0.f;
    for (int b = 0; b < nblk; b++) {
        P += g_Ppart[b * E + e];
        M += g_Mpart[b * E + e];
    }
    g_P[e] = P; g_M[e] = M;
    float Tf = (float)T;
    s[e] = (M / Tf) * (P / Tf);
    __syncthreads();
    if (e == 0) {
        float acc = 0.f;
        for (int i = 0; i < E; i++) acc += s[i];
        float aux = 0.01f * 64.0f * acc;
        if (out_size > T * E) out[(size_t)T * E] = aux;
    }
}

// ---- capacity fixup (fast path: one LDG per token) ----
__global__ void fixup_kernel(float* __restrict__ out, int T, float cap)
{
    int t = blockIdx.x * blockDim.x + threadIdx.x;
    if (t >= T) return;
    int e = g_topidx[t];
    float M = g_M[e];
    if (M <= cap) return;
    float p = g_topprob[t];
    float prefix = 0.f;
    for (int t2 = 0; t2 < T; t2++) {
        if (g_topidx[t2] == e) {
            float p2 = g_topprob[t2];
            if (p2 > p || (p2 == p && t2 <= t)) prefix += p2;
        }
    }
    if (prefix > cap) {
#pragma unroll
        for (int j = 0; j < E; j++) out[(size_t)t * E + j] = 0.f;
    }
}

extern "C" void kernel_launch(void* const* d_in, const int* in_sizes, int n_in,
                              void* d_out, int out_size)
{
    const float* x    = (const float*)d_in[0];
    const float* W    = (const float*)d_in[1];
    const float* bias = (const float*)d_in[2];
    float* out = (float*)d_out;

    int T = in_sizes[0] / D;                          // 16384
    int nblk = T / BM;                                // 256
    float cap = (float)(int)((double)T / (double)E);  // 256

    wsplit_kernel<<<E, 256>>>(W);
    router_kernel<<<nblk, NT>>>(x, bias, out, T);
    reduce_kernel<<<1, E>>>(out, T, nblk, out_size);
    fixup_kernel<<<(T + 255) / 256, 256>>>(out, T, cap);
}

// round 10
// speedup vs baseline: 3.2999x; 1.0298x over previous
#include <cuda_runtime.h>
#include <cuda_fp16.h>
#include <cstdint>

#define D 4096
#define E 64
#define BM 64            // tokens per CTA
#define BK 64            // k per chunk
#define NT 256
#define NCHUNK (D / BK)  // 64
#define AST 72           // smem row stride in fp16 elems (144 B)
#define MAXBLK 256
#define MAXT 16384

// ---- device scratch ----
__device__ __half g_whT[E * D];          // W^T fp16  [n][k]
__device__ float g_Ppart[MAXBLK * E];
__device__ float g_Mpart[MAXBLK * E];
__device__ int   g_topidx[MAXT];
__device__ float g_topprob[MAXT];

__device__ __forceinline__ uint32_t smem_u32(const void* p) {
    uint32_t a;
    asm("{ .reg .u64 t; cvta.to.shared.u64 t, %1; cvt.u32.u64 %0, t; }"
        : "=r"(a) : "l"(p));
    return a;
}

__device__ __forceinline__ void ldsm_x4(uint32_t& r0, uint32_t& r1,
                                        uint32_t& r2, uint32_t& r3, uint32_t addr) {
    asm volatile("ldmatrix.sync.aligned.m8n8.x4.shared.b16 {%0,%1,%2,%3}, [%4];"
                 : "=r"(r0), "=r"(r1), "=r"(r2), "=r"(r3) : "r"(addr));
}

__device__ __forceinline__ void mma_f16(float* c, const uint32_t* a,
                                        uint32_t b0, uint32_t b1) {
    asm volatile(
        "mma.sync.aligned.m16n8k16.row.col.f32.f16.f16.f32 "
        "{%0,%1,%2,%3}, {%4,%5,%6,%7}, {%8,%9}, {%0,%1,%2,%3};"
        : "+f"(c[0]), "+f"(c[1]), "+f"(c[2]), "+f"(c[3])
        : "r"(a[0]), "r"(a[1]), "r"(a[2]), "r"(a[3]), "r"(b0), "r"(b1));
}

__device__ __forceinline__ uint32_t cvt2h(float a, float b) {
    __half2 h = __floats2half2_rn(a, b);
    return *(uint32_t*)&h;
}

// ---- W transpose to fp16, coalesced via smem tile ----
__global__ void wsplit_kernel(const float* __restrict__ W) {
    __shared__ float tile[64][65];
    const int k0 = blockIdx.x * 64;
    const int tid = threadIdx.x;          // 256
#pragma unroll
    for (int j = 0; j < 16; j++) {
        int k = j * 4 + (tid >> 6);
        int n = tid & 63;
        tile[k][n] = W[(size_t)(k0 + k) * E + n];
    }
    __syncthreads();
#pragma unroll
    for (int j = 0; j < 16; j++) {
        int n = j * 4 + (tid >> 6);
        int k = tid & 63;
        g_whT[(size_t)n * D + k0 + k] = __float2half_rn(tile[k][n]);
    }
}

// ---- fused router: HMMA fp16 GEMM + softmax + top1 + partials ----
__global__ __launch_bounds__(NT, 2) void router_kernel(
    const float* __restrict__ x, const float* __restrict__ bias,
    float* __restrict__ out, int T)
{
    __shared__ union {
        struct {
            __align__(16) unsigned short ah[2][BM * AST];   // 2 x 9216 B
            __align__(16) unsigned short bh[2][E * AST];    // 2 x 9216 B
        } t;                                     // 36864 B
        float lsm[BM][E + 1];                    // 16640 B (overlay)
    } smA;
    __shared__ float bs[E];
    __shared__ float red_m[BM], red_s[BM], red_p[BM];
    __shared__ int   red_i[BM];
    __shared__ float Pp[4][E];

    const int tid = threadIdx.x;
    const int wid = tid >> 5;
    const int lid = tid & 31;
    const size_t t0 = (size_t)blockIdx.x * BM;

    if (tid < E) bs[tid] = bias[tid];

    // load geometry: row = tid>>2 (0..63), kq = tid&3 (16 k-values each)
    const int row = tid >> 2;
    const int kq  = tid & 3;
    const float* xg = x + (t0 + row) * D + kq * 16;
    const unsigned char* whg = (const unsigned char*)g_whT + (size_t)row * D * 2 + kq * 32;

    // warp tile: m16 x n32
    const int m_base = (wid >> 1) * 16;
    const int n_base = (wid & 1) * 32;

    const uint32_t ahb[2] = { smem_u32(&smA.t.ah[0][0]), smem_u32(&smA.t.ah[1][0]) };
    const uint32_t bhb[2] = { smem_u32(&smA.t.bh[0][0]), smem_u32(&smA.t.bh[1][0]) };

    // per-lane ldmatrix row offsets (row stride 144 B)
    const int lg  = lid >> 3;
    const int lr  = lid & 7;
    const uint32_t a_off = (uint32_t)((m_base + (lg & 1) * 8 + lr) * 144 + (lg >> 1) * 16);
    const uint32_t b_off0 = (uint32_t)((n_base + (lg >> 1) * 8 + lr) * 144 + (lg & 1) * 16);
    const uint32_t b_off1 = b_off0 + 16 * 144;

    float acc[4][4];
#pragma unroll
    for (int f = 0; f < 4; f++)
#pragma unroll
        for (int q = 0; q < 4; q++) acc[f][q] = 0.f;

    const uint32_t st_off = (uint32_t)(row * 144 + kq * 32);   // per-thread STS base

    // stage registers (two chunks in flight)
    float4 xva[4], xvb[4]; uint4 bva[2], bvb[2];

#define LOAD_REGS(xv, bv, chunk) do {                                           \
        const int _k0 = (chunk) * BK;                                           \
        _Pragma("unroll")                                                       \
        for (int _j = 0; _j < 4; _j++) xv[_j] = *(const float4*)(xg + _k0 + _j * 4); \
        _Pragma("unroll")                                                       \
        for (int _j = 0; _j < 2; _j++) bv[_j] = *(const uint4*)(whg + _k0 * 2 + _j * 16); \
    } while (0)

#define STORE_TILE(bufi, xv, bv) do {                                           \
        uint4 _q0 = make_uint4(cvt2h(xv[0].x, xv[0].y), cvt2h(xv[0].z, xv[0].w), \
                               cvt2h(xv[1].x, xv[1].y), cvt2h(xv[1].z, xv[1].w)); \
        uint4 _q1 = make_uint4(cvt2h(xv[2].x, xv[2].y), cvt2h(xv[2].z, xv[2].w), \
                               cvt2h(xv[3].x, xv[3].y), cvt2h(xv[3].z, xv[3].w)); \
        *(uint4*)((unsigned char*)&smA.t.ah[bufi][0] + st_off)      = _q0;      \
        *(uint4*)((unsigned char*)&smA.t.ah[bufi][0] + st_off + 16) = _q1;      \
        *(uint4*)((unsigned char*)&smA.t.bh[bufi][0] + st_off)      = bv[0];    \
        *(uint4*)((unsigned char*)&smA.t.bh[bufi][0] + st_off + 16) = bv[1];    \
    } while (0)

#define COMPUTE(bufi) do {                                                      \
        _Pragma("unroll")                                                       \
        for (int _ks = 0; _ks < 4; _ks++) {                                     \
            const uint32_t _ko = (uint32_t)(_ks * 32);                          \
            uint32_t _a4[4], _b8[8];                                            \
            ldsm_x4(_a4[0], _a4[1], _a4[2], _a4[3], ahb[bufi] + a_off + _ko);   \
            ldsm_x4(_b8[0], _b8[1], _b8[2], _b8[3], bhb[bufi] + b_off0 + _ko);  \
            ldsm_x4(_b8[4], _b8[5], _b8[6], _b8[7], bhb[bufi] + b_off1 + _ko);  \
            _Pragma("unroll")                                                   \
            for (int _f = 0; _f < 4; _f++)                                      \
                mma_f16(acc[_f], _a4, _b8[2 * _f], _b8[2 * _f + 1]);            \
        }                                                                       \
    } while (0)

    // ---- prologue: chunk0 -> buf0; chunk1 -> regs a ----
    LOAD_REGS(xva, bva, 0);
    STORE_TILE(0, xva, bva);
    LOAD_REGS(xva, bva, 1);
    __syncthreads();

    // ---- mainloop, unrolled by 2 (depth-2 prefetch) ----
#pragma unroll 1
    for (int i = 0; i < NCHUNK; i += 2) {
        // first half: compute chunk i (buf0), store chunk i+1 (regs a -> buf1)
        if (i + 2 < NCHUNK) LOAD_REGS(xvb, bvb, i + 2);
        COMPUTE(0);
        STORE_TILE(1, xva, bva);
        __syncthreads();
        // second half: compute chunk i+1 (buf1), store chunk i+2 (regs b -> buf0)
        if (i + 3 < NCHUNK) LOAD_REGS(xva, bva, i + 3);
        COMPUTE(1);
        if (i + 2 < NCHUNK) STORE_TILE(0, xvb, bvb);
        __syncthreads();
    }

    // ---- spill logits to smem (tiles now dead) ----
    {
        const int mr = m_base + (lid >> 2);
        const int nc = n_base + (lid & 3) * 2;
#pragma unroll
        for (int f = 0; f < 4; f++) {
            smA.lsm[mr][nc + f * 8]         = acc[f][0];
            smA.lsm[mr][nc + f * 8 + 1]     = acc[f][1];
            smA.lsm[mr + 8][nc + f * 8]     = acc[f][2];
            smA.lsm[mr + 8][nc + f * 8 + 1] = acc[f][3];
        }
    }
    __syncthreads();

    // phase 1: per-token max / first-index argmax / 1/sum(exp)
    if (tid < BM) {
        int t = tid;
        float m = -1e30f; int bi = 0;
#pragma unroll 8
        for (int e = 0; e < E; e++) {
            float v = smA.lsm[t][e] + bs[e];
            if (v > m) { m = v; bi = e; }     // strict '>' => first occurrence
        }
        float ssum = 0.f;
#pragma unroll 8
        for (int e = 0; e < E; e++)
            ssum += __expf(smA.lsm[t][e] + bs[e] - m);
        float rs = 1.0f / ssum;               // top-1 prob
        red_m[t] = m; red_s[t] = rs; red_i[t] = bi; red_p[t] = rs;
        g_topidx[t0 + t]  = bi;
        g_topprob[t0 + t] = rs;
    }
    __syncthreads();

    // phase 2: write softmax probs; per-expert P partials
    {
        int e  = tid & 63;
        int th = tid >> 6;                     // 0..3, 16 tokens each
        float Psum = 0.f;
        float be = bs[e];
        for (int t = th * 16; t < th * 16 + 16; t++) {
            float pv = __expf(smA.lsm[t][e] + be - red_m[t]) * red_s[t];
            out[(t0 + t) * E + e] = pv;
            Psum += pv;
        }
        Pp[th][e] = Psum;
    }
    __syncthreads();

    if (tid < E) {
        int e = tid;
        float Msum = 0.f;
        for (int t = 0; t < BM; t++)
            if (red_i[t] == e) Msum += red_p[t];
        g_Ppart[blockIdx.x * E + e] = Pp[0][e] + Pp[1][e] + Pp[2][e] + Pp[3][e];
        g_Mpart[blockIdx.x * E + e] = Msum;
    }
#undef LOAD_REGS
#undef STORE_TILE
#undef COMPUTE
}

// ---- merged finish: reduce partials (per-block, redundant) + aux + capacity fixup ----
__global__ void finish_kernel(float* __restrict__ out, int T, int nblk,
                              int out_size, float cap)
{
    __shared__ float sM[E], sP[E];
    const int tid = threadIdx.x;            // 256
    if (tid < E) {
        float M = 0.f, P = 0.f;
        for (int b = 0; b < nblk; b++) {
            M += g_Mpart[b * E + tid];
            P += g_Ppart[b * E + tid];
        }
        sM[tid] = M; sP[tid] = P;
    }
    __syncthreads();

    if (blockIdx.x == 0 && tid == 0 && out_size > T * E) {
        float accv = 0.f, Tf = (float)T;
        for (int e = 0; e < E; e++) accv += (sM[e] / Tf) * (sP[e] / Tf);
        out[(size_t)T * E] = 0.01f * 64.0f * accv;
    }

    const int t = blockIdx.x * 256 + tid;
    if (t >= T) return;
    const int e = g_topidx[t];
    if (sM[e] <= cap) return;               // fast path: expert under capacity
    // slow path: exact prefix mass (deterministic tie-break on index)
    float p = g_topprob[t];
    float prefix = 0.f;
    for (int t2 = 0; t2 < T; t2++) {
        if (g_topidx[t2] == e) {
            float p2 = g_topprob[t2];
            if (p2 > p || (p2 == p && t2 <= t)) prefix += p2;
        }
    }
    if (prefix > cap) {
#pragma unroll
        for (int j = 0; j < E; j++) out[(size_t)t * E + j] = 0.f;
    }
}

extern "C" void kernel_launch(void* const* d_in, const int* in_sizes, int n_in,
                              void* d_out, int out_size)
{
    const float* x    = (const float*)d_in[0];
    const float* W    = (const float*)d_in[1];
    const float* bias = (const float*)d_in[2];
    float* out = (float*)d_out;

    int T = in_sizes[0] / D;                          // 16384
    int nblk = T / BM;                                // 256
    float cap = (float)(int)((double)T / (double)E);  // 256

    wsplit_kernel<<<D / 64, 256>>>(W);
    router_kernel<<<nblk, NT>>>(x, bias, out, T);
    finish_kernel<<<(T + 255) / 256, 256>>>(out, T, nblk, out_size, cap);
}

// round 12
// speedup vs baseline: 3.5701x; 1.0819x over previous
#include <cuda_runtime.h>
#include <cuda_fp16.h>
#include <cstdint>

#define D 4096
#define E 64
#define BM 64            // tokens per CTA
#define BK 64            // k per chunk
#define NT 256
#define NCHUNK (D / BK)  // 64
#define AST 72           // smem row stride in fp16 elems (144 B)
#define MAXBLK 256
#define MAXT 16384

// ---- device scratch ----
__device__ __half g_whT[E * D];          // W^T fp16  [n][k]
__device__ float g_Ppart[MAXBLK * E];
__device__ float g_Mpart[MAXBLK * E];
__device__ int   g_topidx[MAXT];
__device__ float g_topprob[MAXT];

__device__ __forceinline__ uint32_t smem_u32(const void* p) {
    uint32_t a;
    asm("{ .reg .u64 t; cvta.to.shared.u64 t, %1; cvt.u32.u64 %0, t; }"
        : "=r"(a) : "l"(p));
    return a;
}

__device__ __forceinline__ void ldsm_x4(uint32_t& r0, uint32_t& r1,
                                        uint32_t& r2, uint32_t& r3, uint32_t addr) {
    asm volatile("ldmatrix.sync.aligned.m8n8.x4.shared.b16 {%0,%1,%2,%3}, [%4];"
                 : "=r"(r0), "=r"(r1), "=r"(r2), "=r"(r3) : "r"(addr));
}

__device__ __forceinline__ void mma_f16(float* c, const uint32_t* a,
                                        uint32_t b0, uint32_t b1) {
    asm volatile(
        "mma.sync.aligned.m16n8k16.row.col.f32.f16.f16.f32 "
        "{%0,%1,%2,%3}, {%4,%5,%6,%7}, {%8,%9}, {%0,%1,%2,%3};"
        : "+f"(c[0]), "+f"(c[1]), "+f"(c[2]), "+f"(c[3])
        : "r"(a[0]), "r"(a[1]), "r"(a[2]), "r"(a[3]), "r"(b0), "r"(b1));
}

__device__ __forceinline__ uint32_t cvt2h(float a, float b) {
    __half2 h = __floats2half2_rn(a, b);
    return *(uint32_t*)&h;
}

// ---- W transpose to fp16, coalesced via smem tile (grid = D/16) ----
__global__ void wsplit_kernel(const float* __restrict__ W) {
    __shared__ float tile[16][65];
    const int k0 = blockIdx.x * 16;
    const int tid = threadIdx.x;          // 256
#pragma unroll
    for (int j = 0; j < 4; j++) {
        int idx = tid + j * 256;
        int k = idx >> 6, n = idx & 63;
        tile[k][n] = W[(size_t)(k0 + k) * E + n];
    }
    __syncthreads();
#pragma unroll
    for (int j = 0; j < 4; j++) {
        int idx = tid + j * 256;
        int n = idx >> 4, k = idx & 15;
        g_whT[(size_t)n * D + k0 + k] = __float2half_rn(tile[k][n]);
    }
}

// ---- fused router: HMMA fp16 GEMM (k-split m32n32 warps) + softmax + top1 ----
__global__ __launch_bounds__(NT, 2) void router_kernel(
    const float* __restrict__ x, const float* __restrict__ bias,
    float* __restrict__ out, int T)
{
    __shared__ union {
        struct {
            __align__(16) unsigned short ah[2][BM * AST];   // 2 x 9216 B
            __align__(16) unsigned short bh[2][E * AST];    // 2 x 9216 B
        } t;                                     // 36864 B
        float lsm[BM][E + 1];                    // 16640 B (overlay)
    } smA;
    __shared__ float bs[E];
    __shared__ float red_m[BM], red_s[BM], red_p[BM];
    __shared__ int   red_i[BM];
    __shared__ float Pp[4][E];

    const int tid = threadIdx.x;
    const int wid = tid >> 5;
    const int lid = tid & 31;
    const size_t t0 = (size_t)blockIdx.x * BM;

    if (tid < E) bs[tid] = bias[tid];

    // load geometry: row = tid>>2 (0..63), kq = tid&3 (16 k-values each)
    const int row = tid >> 2;
    const int kq  = tid & 3;
    const float* xg = x + (t0 + row) * D + kq * 16;
    const unsigned char* whg = (const unsigned char*)g_whT + (size_t)row * D * 2 + kq * 32;

    // warp mapping: tile = wid&3 (m32 x n32), k-group = wid>>2
    const int tw     = wid & 3;
    const int kg     = wid >> 2;
    const int m_base = (tw & 1) * 32;
    const int n_base = (tw >> 1) * 32;
    const uint32_t kbase = (uint32_t)(kg * 64);   // byte offset of this warp's k16 pair

    const uint32_t ahb[2] = { smem_u32(&smA.t.ah[0][0]), smem_u32(&smA.t.ah[1][0]) };
    const uint32_t bhb[2] = { smem_u32(&smA.t.bh[0][0]), smem_u32(&smA.t.bh[1][0]) };

    // per-lane ldmatrix row offsets (row stride 144 B)
    const int lg  = lid >> 3;
    const int lr  = lid & 7;
    const uint32_t a_off  = (uint32_t)((m_base + (lg & 1) * 8 + lr) * 144 + (lg >> 1) * 16);
    const uint32_t a_off2 = a_off + 16 * 144;     // rows m_base+16..31
    const uint32_t b_off0 = (uint32_t)((n_base + (lg >> 1) * 8 + lr) * 144 + (lg & 1) * 16);
    const uint32_t b_off1 = b_off0 + 16 * 144;    // n_base+16..31

    float acc[2][4][4];
#pragma unroll
    for (int h = 0; h < 2; h++)
#pragma unroll
        for (int f = 0; f < 4; f++)
#pragma unroll
            for (int q = 0; q < 4; q++) acc[h][f][q] = 0.f;

    const uint32_t st_off = (uint32_t)(row * 144 + kq * 32);   // per-thread STS base

    float4 xva[4], xvb[4]; uint4 bva[2], bvb[2];

#define LOAD_REGS(xv, bv, chunk) do {                                           \
        const int _k0 = (chunk) * BK;                                           \
        _Pragma("unroll")                                                       \
        for (int _j = 0; _j < 4; _j++) xv[_j] = *(const float4*)(xg + _k0 + _j * 4); \
        _Pragma("unroll")                                                       \
        for (int _j = 0; _j < 2; _j++) bv[_j] = *(const uint4*)(whg + _k0 * 2 + _j * 16); \
    } while (0)

#define STORE_TILE(bufi, xv, bv) do {                                           \
        uint4 _q0 = make_uint4(cvt2h(xv[0].x, xv[0].y), cvt2h(xv[0].z, xv[0].w), \
                               cvt2h(xv[1].x, xv[1].y), cvt2h(xv[1].z, xv[1].w)); \
        uint4 _q1 = make_uint4(cvt2h(xv[2].x, xv[2].y), cvt2h(xv[2].z, xv[2].w), \
                               cvt2h(xv[3].x, xv[3].y), cvt2h(xv[3].z, xv[3].w)); \
        *(uint4*)((unsigned char*)&smA.t.ah[bufi][0] + st_off)      = _q0;      \
        *(uint4*)((unsigned char*)&smA.t.ah[bufi][0] + st_off + 16) = _q1;      \
        *(uint4*)((unsigned char*)&smA.t.bh[bufi][0] + st_off)      = bv[0];    \
        *(uint4*)((unsigned char*)&smA.t.bh[bufi][0] + st_off + 16) = bv[1];    \
    } while (0)

#define COMPUTE(bufi) do {                                                      \
        _Pragma("unroll")                                                       \
        for (int _s = 0; _s < 2; _s++) {                                        \
            const uint32_t _ko = kbase + (uint32_t)(_s * 32);                   \
            uint32_t _a1[4], _a2[4], _b8[8];                                    \
            ldsm_x4(_a1[0], _a1[1], _a1[2], _a1[3], ahb[bufi] + a_off  + _ko);  \
            ldsm_x4(_a2[0], _a2[1], _a2[2], _a2[3], ahb[bufi] + a_off2 + _ko);  \
            ldsm_x4(_b8[0], _b8[1], _b8[2], _b8[3], bhb[bufi] + b_off0 + _ko);  \
            ldsm_x4(_b8[4], _b8[5], _b8[6], _b8[7], bhb[bufi] + b_off1 + _ko);  \
            _Pragma("unroll")                                                   \
            for (int _f = 0; _f < 4; _f++) {                                    \
                mma_f16(acc[0][_f], _a1, _b8[2 * _f], _b8[2 * _f + 1]);         \
                mma_f16(acc[1][_f], _a2, _b8[2 * _f], _b8[2 * _f + 1]);         \
            }                                                                   \
        }                                                                       \
    } while (0)

    // ---- prologue: chunk0 -> buf0; chunk1 -> regs a ----
    LOAD_REGS(xva, bva, 0);
    STORE_TILE(0, xva, bva);
    LOAD_REGS(xva, bva, 1);
    __syncthreads();

    // ---- mainloop, unrolled by 2 (depth-2 prefetch) ----
#pragma unroll 1
    for (int i = 0; i < NCHUNK; i += 2) {
        if (i + 2 < NCHUNK) LOAD_REGS(xvb, bvb, i + 2);
        COMPUTE(0);
        STORE_TILE(1, xva, bva);
        __syncthreads();
        if (i + 3 < NCHUNK) LOAD_REGS(xva, bva, i + 3);
        COMPUTE(1);
        if (i + 2 < NCHUNK) STORE_TILE(0, xvb, bvb);
        __syncthreads();
    }

    // ---- spill logits: kg=0 writes, kg=1 accumulates (k-split reduction) ----
    {
        const int mr = m_base + (lid >> 2);
        const int nc = n_base + (lid & 3) * 2;
        if (kg == 0) {
#pragma unroll
            for (int f = 0; f < 4; f++) {
                smA.lsm[mr][nc + f * 8]          = acc[0][f][0];
                smA.lsm[mr][nc + f * 8 + 1]      = acc[0][f][1];
                smA.lsm[mr + 8][nc + f * 8]      = acc[0][f][2];
                smA.lsm[mr + 8][nc + f * 8 + 1]  = acc[0][f][3];
                smA.lsm[mr + 16][nc + f * 8]     = acc[1][f][0];
                smA.lsm[mr + 16][nc + f * 8 + 1] = acc[1][f][1];
                smA.lsm[mr + 24][nc + f * 8]     = acc[1][f][2];
                smA.lsm[mr + 24][nc + f * 8 + 1] = acc[1][f][3];
            }
        }
        __syncthreads();
        if (kg == 1) {
#pragma unroll
            for (int f = 0; f < 4; f++) {
                smA.lsm[mr][nc + f * 8]          += acc[0][f][0];
                smA.lsm[mr][nc + f * 8 + 1]      += acc[0][f][1];
                smA.lsm[mr + 8][nc + f * 8]      += acc[0][f][2];
                smA.lsm[mr + 8][nc + f * 8 + 1]  += acc[0][f][3];
                smA.lsm[mr + 16][nc + f * 8]     += acc[1][f][0];
                smA.lsm[mr + 16][nc + f * 8 + 1] += acc[1][f][1];
                smA.lsm[mr + 24][nc + f * 8]     += acc[1][f][2];
                smA.lsm[mr + 24][nc + f * 8 + 1] += acc[1][f][3];
            }
        }
    }
    __syncthreads();

    // phase 1: per-token max / first-index argmax / 1/sum(exp)
    if (tid < BM) {
        int t = tid;
        float m = -1e30f; int bi = 0;
#pragma unroll 8
        for (int e = 0; e < E; e++) {
            float v = smA.lsm[t][e] + bs[e];
            if (v > m) { m = v; bi = e; }     // strict '>' => first occurrence
        }
        float ssum = 0.f;
#pragma unroll 8
        for (int e = 0; e < E; e++)
            ssum += __expf(smA.lsm[t][e] + bs[e] - m);
        float rs = 1.0f / ssum;               // top-1 prob
        red_m[t] = m; red_s[t] = rs; red_i[t] = bi; red_p[t] = rs;
        g_topidx[t0 + t]  = bi;
        g_topprob[t0 + t] = rs;
    }
    __syncthreads();

    // phase 2: write softmax probs; per-expert P partials
    {
        int e  = tid & 63;
        int th = tid >> 6;                     // 0..3, 16 tokens each
        float Psum = 0.f;
        float be = bs[e];
        for (int t = th * 16; t < th * 16 + 16; t++) {
            float pv = __expf(smA.lsm[t][e] + be - red_m[t]) * red_s[t];
            out[(t0 + t) * E + e] = pv;
            Psum += pv;
        }
        Pp[th][e] = Psum;
    }
    __syncthreads();

    if (tid < E) {
        int e = tid;
        float Msum = 0.f;
        for (int t = 0; t < BM; t++)
            if (red_i[t] == e) Msum += red_p[t];
        g_Ppart[blockIdx.x * E + e] = Pp[0][e] + Pp[1][e] + Pp[2][e] + Pp[3][e];
        g_Mpart[blockIdx.x * E + e] = Msum;
    }
#undef LOAD_REGS
#undef STORE_TILE
#undef COMPUTE
}

// ---- merged finish: reduce partials (per-block, redundant) + aux + capacity fixup ----
__global__ void finish_kernel(float* __restrict__ out, int T, int nblk,
                              int out_size, float cap)
{
    __shared__ float sM[E], sP[E];
    const int tid = threadIdx.x;            // 256
    if (tid < E) {
        float M = 0.f, P = 0.f;
        for (int b = 0; b < nblk; b++) {
            M += g_Mpart[b * E + tid];
            P += g_Ppart[b * E + tid];
        }
        sM[tid] = M; sP[tid] = P;
    }
    __syncthreads();

    if (blockIdx.x == 0 && tid == 0 && out_size > T * E) {
        float accv = 0.f, Tf = (float)T;
        for (int e = 0; e < E; e++) accv += (sM[e] / Tf) * (sP[e] / Tf);
        out[(size_t)T * E] = 0.01f * 64.0f * accv;
    }

    const int t = blockIdx.x * 256 + tid;
    if (t >= T) return;
    const int e = g_topidx[t];
    if (sM[e] <= cap) return;               // fast path: expert under capacity
    float p = g_topprob[t];
    float prefix = 0.f;
    for (int t2 = 0; t2 < T; t2++) {
        if (g_topidx[t2] == e) {
            float p2 = g_topprob[t2];
            if (p2 > p || (p2 == p && t2 <= t)) prefix += p2;
        }
    }
    if (prefix > cap) {
#pragma unroll
        for (int j = 0; j < E; j++) out[(size_t)t * E + j] = 0.f;
    }
}

extern "C" void kernel_launch(void* const* d_in, const int* in_sizes, int n_in,
                              void* d_out, int out_size)
{
    const float* x    = (const float*)d_in[0];
    const float* W    = (const float*)d_in[1];
    const float* bias = (const float*)d_in[2];
    float* out = (float*)d_out;

    int T = in_sizes[0] / D;                          // 16384
    int nblk = T / BM;                                // 256
    float cap = (float)(int)((double)T / (double)E);  // 256

    wsplit_kernel<<<D / 16, 256>>>(W);
    router_kernel<<<nblk, NT>>>(x, bias, out, T);
    finish_kernel<<<(T + 255) / 256, 256>>>(out, T, nblk, out_size, cap);
}